// round 3
// baseline (speedup 1.0000x reference)
#include <cuda_runtime.h>

// Problem constants (fixed by setup_inputs)
#define BB   2
#define NN   16384
#define CC   64
#define SS   4096
#define KK   32
#define R2   0.16f
#define CIN  67
#define H3   128

#define OUT_F (BB*SS*3)              /* 24576  : new_xyz region     */
#define OUT_I (OUT_F + BB*H3*SS)     /* 1073152: samp_idx region    */

#define AST 70   /* activation buffer k-stride (words), conflict-free */
#define W1S 70   /* W1^T row stride */
#define W2S 66   /* W2^T / W3^T row stride */

// Scratch (device globals — no allocation allowed)
__device__ float4 g_pts[BB*NN];          // x,y,z,|p|^2
__device__ float  g_featT[BB*NN*CC];     // [B][N][C]
__device__ int    g_idx[BB*SS*KK];       // ball query result

// ---- packed f32x2 helpers (FFMA2: 2x fp32 FMA rate, PTX-only) -------------
typedef unsigned long long ull;
__device__ __forceinline__ ull pk2(float lo, float hi) {
    ull r; asm("mov.b64 %0,{%1,%2};" : "=l"(r) : "f"(lo), "f"(hi)); return r;
}
__device__ __forceinline__ void upk2(ull v, float& lo, float& hi) {
    asm("mov.b64 {%0,%1},%2;" : "=f"(lo), "=f"(hi) : "l"(v));
}
__device__ __forceinline__ ull ffma2(ull a, ull b, ull c) {
    ull d; asm("fma.rn.f32x2 %0,%1,%2,%3;" : "=l"(d) : "l"(a), "l"(b), "l"(c));
    return d;
}
__device__ __forceinline__ ull ldp(const float* p) {   // aligned smem pair
    return *reinterpret_cast<const ull*>(p);
}

// ---------------------------------------------------------------------------
__global__ void k_prep(const float* __restrict__ xyz) {
    int i = blockIdx.x * blockDim.x + threadIdx.x;
    if (i < BB*NN) {
        float x = xyz[3*i+0], y = xyz[3*i+1], z = xyz[3*i+2];
        g_pts[i] = make_float4(x, y, z, fmaf(z, z, fmaf(y, y, x*x)));
    }
}

// Transpose features [B,C,N] -> [B,N,C]
__global__ void k_trans(const float* __restrict__ feat) {
    __shared__ float tile[32][33];
    int b  = blockIdx.z;
    int n0 = blockIdx.x * 32, c0 = blockIdx.y * 32;
    int tx = threadIdx.x, ty = threadIdx.y;
    #pragma unroll
    for (int i = ty; i < 32; i += 8)
        tile[i][tx] = feat[(size_t)b*CC*NN + (size_t)(c0+i)*NN + (n0+tx)];
    __syncthreads();
    #pragma unroll
    for (int i = ty; i < 32; i += 8)
        g_featT[(size_t)b*NN*CC + (size_t)(n0+i)*CC + (c0+tx)] = tile[tx][i];
}

// new_xyz copy + samp_idx
__global__ void k_outs(const float* __restrict__ xyz, float* __restrict__ out) {
    int i = blockIdx.x * blockDim.x + threadIdx.x;
    if (i < BB*SS) {
        int b = i / SS, s = i % SS;
        out[3*i+0] = xyz[(size_t)(b*NN+s)*3 + 0];
        out[3*i+1] = xyz[(size_t)(b*NN+s)*3 + 1];
        out[3*i+2] = xyz[(size_t)(b*NN+s)*3 + 2];
        out[OUT_I + i] = (float)s;
    }
}

// ---------------------------------------------------------------------------
// Ball query: one warp per centroid, unrolled x8 (MLP=8, latency-bound).
// Ordered scan; ballot+popc assigns the first KK in-index-order hits; early
// exit every 256 points. Matches reference semantics exactly.
__global__ void k_ball() {
    __shared__ int sbuf[8][KK];
    int w    = threadIdx.x >> 5;
    int lane = threadIdx.x & 31;
    int gw   = blockIdx.x * 8 + w;
    int b    = gw / SS, s = gw % SS;
    int base0 = b * NN;
    float4 c4 = g_pts[base0 + s];
    unsigned lmask = (1u << lane) - 1u;
    unsigned lbit  = 1u << lane;
    int cnt = 0;
    for (int base = 0; base < NN; base += 256) {
        float4 p[8];
        #pragma unroll
        for (int u = 0; u < 8; u++)
            p[u] = g_pts[base0 + base + 32*u + lane];
        float d2[8];
        #pragma unroll
        for (int u = 0; u < 8; u++)
            d2[u] = c4.w + p[u].w - 2.0f*(c4.x*p[u].x + c4.y*p[u].y + c4.z*p[u].z);
        #pragma unroll
        for (int u = 0; u < 8; u++) {
            unsigned m = __ballot_sync(0xffffffffu, d2[u] < R2);
            if (m & lbit) {
                int pos = cnt + __popc(m & lmask);
                if (pos < KK) sbuf[w][pos] = base + 32*u + lane;
            }
            cnt += __popc(m);
        }
        if (cnt >= KK) break;
    }
    __syncwarp();
    int v = 0;
    if (cnt > 0) {
        int first = sbuf[w][0];
        v = (lane < cnt) ? sbuf[w][lane] : first;
    }
    g_idx[gw*KK + lane] = v;
}

// ---------------------------------------------------------------------------
// Fused gather + 3-layer MLP + max-pool, FFMA2 packed along the REDUCTION dim:
// acc(k,d) pair accumulates (even-c, odd-c) partial sums; both operands are
// adjacent-pair LDS.64 (activations [k][c]-major, weights transposed [d][c]).
// Zero register packs in the hot loop. Epilogue adds the two lanes + bias.
__global__ void __launch_bounds__(128) k_mlp(
    const float* __restrict__ W1, const float* __restrict__ b1,
    const float* __restrict__ W2, const float* __restrict__ b2,
    const float* __restrict__ W3, const float* __restrict__ b3,
    float* __restrict__ out)
{
    extern __shared__ float sm[];
    float* sW1t = sm;                  // 64 x 70  = 4480   W1^T[d][c], c padded
    float* sW2t = sW1t + 64*W1S;       // 64 x 66  = 4224   W2^T[d][c]
    float* sW3t = sW2t + 64*W2S;       // 128 x 66 = 8448   W3^T[d][c]
    float* sb1  = sW3t + 128*W2S;      // 64
    float* sb2  = sb1 + 64;            // 64
    float* sb3  = sb2 + 64;            // 128
    float* bufA = sb3 + 128;           // 32 x 70 = 2240
    float* bufB = bufA + 32*AST;       // 32 x 70 = 2240
    float* red  = bufB + 32*AST;       // 8 x 128 = 1024
    const int tid = threadIdx.x;

    // load transposed weights (coalesced over d)
    for (int i = tid; i < 64*68; i += 128) {
        int d = i & 63, c = i >> 6;
        sW1t[d*W1S + c] = (c < CIN) ? W1[c*64 + d] : 0.f;
    }
    for (int i = tid; i < 64*64; i += 128) {
        int d = i & 63, c = i >> 6;
        sW2t[d*W2S + c] = W2[c*64 + d];
    }
    for (int i = tid; i < 128*64; i += 128) {
        int d = i & 127, c = i >> 7;
        sW3t[d*W2S + c] = W3[c*128 + d];
    }
    if (tid < 64) { sb1[tid] = b1[tid]; sb2[tid] = b2[tid]; }
    sb3[tid] = b3[tid];
    __syncthreads();

    const int dg = tid & 15;          // d lane (0..15); d = dg + 16*j
    const int kg = tid >> 4;          // k group (0..7); k = kg + 8*i
    const int kq = tid >> 2;          // gather: k (0..31)
    const int c0 = tid & 3;           // gather: lane within k

    for (int cent = blockIdx.x; cent < BB*SS; cent += gridDim.x) {
        const int b  = cent >> 12;
        const int s  = cent & (SS-1);
        const int bN = b * NN;

        // ---- gather g[k][0:67] = [dxyz | features]; pad slot 67 = 0 ----
        {
            int n = g_idx[cent*KK + kq];
            float4 p   = g_pts[bN + n];
            float4 ctr = g_pts[bN + s];
            if      (c0 == 0) bufA[kq*AST + 0] = p.x - ctr.x;
            else if (c0 == 1) bufA[kq*AST + 1] = p.y - ctr.y;
            else if (c0 == 2) bufA[kq*AST + 2] = p.z - ctr.z;
            else              bufA[kq*AST + 67] = 0.f;
            const float* fr = g_featT + (size_t)(bN + n) * CC;
            #pragma unroll
            for (int i2 = 0; i2 < 16; i2++) {
                int f = c0 + 4*i2;
                bufA[kq*AST + 3 + f] = fr[f];
            }
        }
        __syncthreads();

        // ---- layer 1: bufA(68 padded) -> bufB(64), relu ----
        {
            ull acc[4][4];
            #pragma unroll
            for (int j = 0; j < 4; j++) {
                ull bi = pk2(sb1[dg + 16*j], 0.f);
                #pragma unroll
                for (int i = 0; i < 4; i++) acc[i][j] = bi;
            }
            for (int cp = 0; cp < 34; cp++) {
                ull av[4], wv[4];
                #pragma unroll
                for (int i = 0; i < 4; i++) av[i] = ldp(bufA + (kg + 8*i)*AST + 2*cp);
                #pragma unroll
                for (int j = 0; j < 4; j++) wv[j] = ldp(sW1t + (dg + 16*j)*W1S + 2*cp);
                #pragma unroll
                for (int i = 0; i < 4; i++)
                    #pragma unroll
                    for (int j = 0; j < 4; j++)
                        acc[i][j] = ffma2(av[i], wv[j], acc[i][j]);
            }
            #pragma unroll
            for (int i = 0; i < 4; i++)
                #pragma unroll
                for (int j = 0; j < 4; j++) {
                    float lo, hi; upk2(acc[i][j], lo, hi);
                    bufB[(kg + 8*i)*AST + dg + 16*j] = fmaxf(lo + hi, 0.f);
                }
        }
        __syncthreads();

        // ---- layer 2: bufB(64) -> bufA(64), relu ----
        {
            ull acc[4][4];
            #pragma unroll
            for (int j = 0; j < 4; j++) {
                ull bi = pk2(sb2[dg + 16*j], 0.f);
                #pragma unroll
                for (int i = 0; i < 4; i++) acc[i][j] = bi;
            }
            for (int cp = 0; cp < 32; cp++) {
                ull av[4], wv[4];
                #pragma unroll
                for (int i = 0; i < 4; i++) av[i] = ldp(bufB + (kg + 8*i)*AST + 2*cp);
                #pragma unroll
                for (int j = 0; j < 4; j++) wv[j] = ldp(sW2t + (dg + 16*j)*W2S + 2*cp);
                #pragma unroll
                for (int i = 0; i < 4; i++)
                    #pragma unroll
                    for (int j = 0; j < 4; j++)
                        acc[i][j] = ffma2(av[i], wv[j], acc[i][j]);
            }
            #pragma unroll
            for (int i = 0; i < 4; i++)
                #pragma unroll
                for (int j = 0; j < 4; j++) {
                    float lo, hi; upk2(acc[i][j], lo, hi);
                    bufA[(kg + 8*i)*AST + dg + 16*j] = fmaxf(lo + hi, 0.f);
                }
        }
        __syncthreads();

        // ---- layer 3: bufA(64) -> 128 outs, relu, partial max over 4 k ----
        {
            ull acc[4][8];
            #pragma unroll
            for (int j = 0; j < 8; j++) {
                ull bi = pk2(sb3[dg + 16*j], 0.f);
                #pragma unroll
                for (int i = 0; i < 4; i++) acc[i][j] = bi;
            }
            for (int cp = 0; cp < 32; cp++) {
                ull av[4], wv[8];
                #pragma unroll
                for (int i = 0; i < 4; i++) av[i] = ldp(bufA + (kg + 8*i)*AST + 2*cp);
                #pragma unroll
                for (int j = 0; j < 8; j++) wv[j] = ldp(sW3t + (dg + 16*j)*W2S + 2*cp);
                #pragma unroll
                for (int i = 0; i < 4; i++)
                    #pragma unroll
                    for (int j = 0; j < 8; j++)
                        acc[i][j] = ffma2(av[i], wv[j], acc[i][j]);
            }
            #pragma unroll
            for (int j = 0; j < 8; j++) {
                float lo, hi, m = 0.f;
                #pragma unroll
                for (int i = 0; i < 4; i++) {
                    upk2(acc[i][j], lo, hi);
                    m = fmaxf(m, lo + hi);
                }
                red[kg*128 + dg + 16*j] = m;   // relu folded: m >= 0 via max(.,0) init
            }
        }
        __syncthreads();

        // ---- final max across the 8 k-groups; write new_features [B,128,S] ----
        {
            float m = red[tid];
            #pragma unroll
            for (int g = 1; g < 8; g++) m = fmaxf(m, red[g*128 + tid]);
            out[OUT_F + (size_t)b*H3*SS + (size_t)tid*SS + s] = m;
        }
        __syncthreads();
    }
}

// ---------------------------------------------------------------------------
extern "C" void kernel_launch(void* const* d_in, const int* in_sizes, int n_in,
                              void* d_out, int out_size) {
    (void)in_sizes; (void)n_in; (void)out_size;
    const float* xyz  = (const float*)d_in[0];
    const float* feat = (const float*)d_in[1];
    const float* W1   = (const float*)d_in[2];
    const float* b1   = (const float*)d_in[3];
    const float* W2   = (const float*)d_in[4];
    const float* b2   = (const float*)d_in[5];
    const float* W3   = (const float*)d_in[6];
    const float* b3   = (const float*)d_in[7];
    float* out = (float*)d_out;

    // smem: 4480+4224+8448+256+2240+2240+1024 = 22912 floats = 91648 B
    const int smem_mlp = 22912 * 4;
    cudaFuncSetAttribute(k_mlp, cudaFuncAttributeMaxDynamicSharedMemorySize, smem_mlp);

    k_prep<<<(BB*NN + 255)/256, 256>>>(xyz);
    k_trans<<<dim3(NN/32, CC/32, BB), dim3(32, 8)>>>(feat);
    k_outs<<<(BB*SS + 255)/256, 256>>>(xyz, out);
    k_ball<<<(BB*SS)/8, 256>>>();
    k_mlp<<<296, 128, smem_mlp>>>(W1, b1, W2, b2, W3, b3, out);
}